// round 5
// baseline (speedup 1.0000x reference)
#include <cuda_runtime.h>
#include <cuda_bf16.h>
#include <cstdint>

// ---------------- problem constants ----------------
#define BATCH 128
#define IN1   3072
#define HID   256
#define OUT2  10
#define NB    8
#define KSPL  (IN1*NB)        // 24576 : spline K region
#define KTOT  (KSPL + IN1)    // 27648 : + silu column region
#define CHUNK 768             // K per split
#define NSPLIT 36             // 36*768 = 27648 ; splits 0..31 coef, 32..35 silu
#define NTILE_N 4             // 4 * 64 = 256

// ---------------- GEMM tiling ----------------
#define BM 128
#define BN 64
#define BK 64
#define APITCH 72             // padded bf16 row pitch (144B) -> conflict-free frag LDS
#define NITER (CHUNK/BK)      // 12
#define SMEM_BYTES (2*BM*APITCH*2 + 2*BN*APITCH*2)  // 55296

// ---------------- static scratch (no allocations allowed) ----------------
__device__ __align__(16) __nv_bfloat16 g_A[(size_t)BATCH * KTOT];          // 7.08 MB
__device__ __align__(16) float         g_P[(size_t)NSPLIT * BATCH * HID];  // 4.72 MB

// ---------------- helpers ----------------
__device__ __forceinline__ uint32_t f2bf2(float lo, float hi) {
    __nv_bfloat162 h = __floats2bfloat162_rn(lo, hi);   // .x = lo (low 16 bits)
    return *reinterpret_cast<uint32_t*>(&h);
}

// Cox-de Boor recursion identical in structure to the reference (k=3, num=5).
// grid[j] = -2.2 + 0.4*j, 12 knots. Result in b[0..7].
__device__ __forceinline__ void bspline8(float xv, float* b) {
#pragma unroll
    for (int j = 0; j < 11; ++j) {
        float gj = -2.2f + 0.4f * j;
        b[j] = (xv >= gj && xv < gj + 0.4f) ? 1.0f : 0.0f;
    }
#pragma unroll
    for (int d = 1; d <= 3; ++d) {
        float inv = 1.0f / (0.4f * d);
#pragma unroll
        for (int j = 0; j < 10; ++j) {
            if (j < 11 - d) {
                float gj = -2.2f + 0.4f * j;
                float left  = (xv - gj) * inv;
                float right = ((gj + 0.4f * (d + 1)) - xv) * inv;
                b[j] = left * b[j] + right * b[j + 1];
            }
        }
    }
}

__device__ __forceinline__ void mma_bf16(float* d, const uint32_t* a, const uint32_t* b) {
    asm volatile(
        "mma.sync.aligned.m16n8k16.row.col.f32.bf16.bf16.f32 "
        "{%0,%1,%2,%3}, {%4,%5,%6,%7}, {%8,%9}, {%0,%1,%2,%3};\n"
        : "+f"(d[0]), "+f"(d[1]), "+f"(d[2]), "+f"(d[3])
        : "r"(a[0]), "r"(a[1]), "r"(a[2]), "r"(a[3]), "r"(b[0]), "r"(b[1]));
}

// ---------------- kernel 1: basis / silu -> A (bf16) ----------------
__global__ void basis_kernel(const float* __restrict__ x) {
    int idx = blockIdx.x * blockDim.x + threadIdx.x;
    if (idx >= BATCH * IN1) return;
    int bi = idx / IN1;
    int i  = idx - bi * IN1;
    float xv = x[idx];

    float sig = 1.0f / (1.0f + expf(-xv));
    float sl  = xv * sig;                 // silu(x)

    float bb[11];
    bspline8(xv, bb);

    __nv_bfloat16* dst = g_A + (size_t)bi * KTOT + (size_t)i * NB;
    uint4 pk;
    pk.x = f2bf2(bb[0], bb[1]);
    pk.y = f2bf2(bb[2], bb[3]);
    pk.z = f2bf2(bb[4], bb[5]);
    pk.w = f2bf2(bb[6], bb[7]);
    *reinterpret_cast<uint4*>(dst) = pk;

    g_A[(size_t)bi * KTOT + KSPL + i] = __float2bfloat16_rn(sl);
}

// ---------------- kernel 2: split-K bf16 MMA GEMM ----------------
// C[b, o] partial = A[b, kchunk] * B[o, kchunk]^T ; B built on the fly from
// coef1*ssp1 (splits 0..31) or sb1 (splits 32..35). Partials -> g_P[split].
extern __shared__ __align__(16) __nv_bfloat16 smem_[];

__global__ void __launch_bounds__(256) gemm_kernel(const float* __restrict__ coef1,
                                                   const float* __restrict__ ssp1,
                                                   const float* __restrict__ sb1) {
    __nv_bfloat16* As = smem_;
    __nv_bfloat16* Bs = smem_ + 2 * BM * APITCH;

    const int tid  = threadIdx.x;
    const int lane = tid & 31;
    const int warp = tid >> 5;
    const int wm   = warp & 3;       // 4 warps along M
    const int wn   = warp >> 2;      // 2 warps along N
    const int n0   = blockIdx.x * BN;
    const int split = blockIdx.y;
    const int kg0   = split * CHUNK;
    const bool coefR = (split < 32);

    // B loader mapping: thread -> (n row, 16-float k segment)
    const int tn = tid >> 2;          // 0..63
    const int tk = (tid & 3) << 4;    // 0,16,32,48

    // A loader mapping: thread -> (row, 32-bf16 half-row)
    const int ar = tid >> 1;          // 0..127
    const int ac = (tid & 1) << 5;    // 0 or 32
    const __nv_bfloat16* aSrcBase = g_A + (size_t)ar * KTOT + kg0 + ac;
    const uint32_t aDstBase =
        (uint32_t)__cvta_generic_to_shared(As) + (uint32_t)(ar * APITCH + ac) * 2;

    float4 breg[4];
    float acc[2][4][4];
#pragma unroll
    for (int mt = 0; mt < 2; ++mt)
#pragma unroll
        for (int nt = 0; nt < 4; ++nt)
#pragma unroll
            for (int q = 0; q < 4; ++q) acc[mt][nt][q] = 0.0f;

    auto ldgB = [&](int it) {
        const int kg = kg0 + it * BK + tk;
        if (coefR) {
            // B[n][k] = coef1[n*24576 + k] * ssp1[n*3072 + (k>>3)]
            const float* p = coef1 + (size_t)(n0 + tn) * KSPL + kg;
            const float s0 = ssp1[(n0 + tn) * IN1 + (kg >> 3)];
            const float s1 = ssp1[(n0 + tn) * IN1 + (kg >> 3) + 1];
            float4 v0 = reinterpret_cast<const float4*>(p)[0];
            float4 v1 = reinterpret_cast<const float4*>(p)[1];
            float4 v2 = reinterpret_cast<const float4*>(p)[2];
            float4 v3 = reinterpret_cast<const float4*>(p)[3];
            breg[0] = make_float4(v0.x * s0, v0.y * s0, v0.z * s0, v0.w * s0);
            breg[1] = make_float4(v1.x * s0, v1.y * s0, v1.z * s0, v1.w * s0);
            breg[2] = make_float4(v2.x * s1, v2.y * s1, v2.z * s1, v2.w * s1);
            breg[3] = make_float4(v3.x * s1, v3.y * s1, v3.z * s1, v3.w * s1);
        } else {
            // silu region: B[n][k] = sb1[n*3072 + (k - 24576)]
            const float* p = sb1 + (size_t)(n0 + tn) * IN1 + (kg - KSPL);
            breg[0] = reinterpret_cast<const float4*>(p)[0];
            breg[1] = reinterpret_cast<const float4*>(p)[1];
            breg[2] = reinterpret_cast<const float4*>(p)[2];
            breg[3] = reinterpret_cast<const float4*>(p)[3];
        }
    };

    auto cpA = [&](int it, int bufd) {
        const __nv_bfloat16* src = aSrcBase + it * BK;
        uint32_t dst = aDstBase + (uint32_t)bufd * (BM * APITCH * 2);
#pragma unroll
        for (int j = 0; j < 8; ++j) {
            asm volatile("cp.async.ca.shared.global [%0], [%1], 8;\n"
                         :: "r"(dst + j * 8), "l"(src + j * 4) : "memory");
        }
    };

    // precomputed fragment row offsets (uint32 indices into padded smem)
    const int fg = lane >> 2, ft = lane & 3;
    int aRow[2][2], bRow[4];
#pragma unroll
    for (int mt = 0; mt < 2; ++mt) {
        aRow[mt][0] = (wm * 32 + mt * 16 + fg) * (APITCH / 2);
        aRow[mt][1] = (wm * 32 + mt * 16 + 8 + fg) * (APITCH / 2);
    }
#pragma unroll
    for (int nt = 0; nt < 4; ++nt) bRow[nt] = (wn * 32 + nt * 8 + fg) * (APITCH / 2);

    // prologue
    ldgB(0);
    cpA(0, 0);
    asm volatile("cp.async.commit_group;\n" ::: "memory");

    for (int it = 0; it < NITER; ++it) {
        const int buf = it & 1;
        asm volatile("cp.async.wait_group 0;\n" ::: "memory");
        // stage B regs -> smem (fp32 -> bf16)
        {
            __nv_bfloat16* d = Bs + buf * BN * APITCH + tn * APITCH + tk;
#pragma unroll
            for (int q = 0; q < 4; ++q) {
                uint2 u;
                u.x = f2bf2(breg[q].x, breg[q].y);
                u.y = f2bf2(breg[q].z, breg[q].w);
                *reinterpret_cast<uint2*>(d + q * 4) = u;
            }
        }
        __syncthreads();
        if (it + 1 < NITER) {
            ldgB(it + 1);
            cpA(it + 1, buf ^ 1);
            asm volatile("cp.async.commit_group;\n" ::: "memory");
        }
        // compute on current buffer
        {
            const uint32_t* A32 = reinterpret_cast<const uint32_t*>(As + buf * BM * APITCH);
            const uint32_t* B32 = reinterpret_cast<const uint32_t*>(Bs + buf * BN * APITCH);
#pragma unroll
            for (int ks = 0; ks < 4; ++ks) {
                const int kh = ks * 8;
                uint32_t af[2][4];
#pragma unroll
                for (int mt = 0; mt < 2; ++mt) {
                    af[mt][0] = A32[aRow[mt][0] + kh + ft];
                    af[mt][1] = A32[aRow[mt][1] + kh + ft];
                    af[mt][2] = A32[aRow[mt][0] + kh + 4 + ft];
                    af[mt][3] = A32[aRow[mt][1] + kh + 4 + ft];
                }
                uint32_t bfr[4][2];
#pragma unroll
                for (int nt = 0; nt < 4; ++nt) {
                    bfr[nt][0] = B32[bRow[nt] + kh + ft];
                    bfr[nt][1] = B32[bRow[nt] + kh + 4 + ft];
                }
#pragma unroll
                for (int mt = 0; mt < 2; ++mt)
#pragma unroll
                    for (int nt = 0; nt < 4; ++nt)
                        mma_bf16(acc[mt][nt], af[mt], bfr[nt]);
            }
        }
    }

    // epilogue: deterministic partial store
    float* Pp = g_P + (size_t)split * BATCH * HID;
#pragma unroll
    for (int mt = 0; mt < 2; ++mt) {
#pragma unroll
        for (int nt = 0; nt < 4; ++nt) {
            int row = wm * 32 + mt * 16 + fg;
            int col = n0 + wn * 32 + nt * 8 + ft * 2;
            float2 v01 = make_float2(acc[mt][nt][0], acc[mt][nt][1]);
            float2 v23 = make_float2(acc[mt][nt][2], acc[mt][nt][3]);
            *reinterpret_cast<float2*>(&Pp[row * HID + col]) = v01;
            *reinterpret_cast<float2*>(&Pp[(row + 8) * HID + col]) = v23;
        }
    }
}

// ---------------- kernel 3: reduce partials, selu, full layer 2 ----------------
__global__ void __launch_bounds__(256) layer2_kernel(const float* __restrict__ coef2,
                                                     const float* __restrict__ sb2,
                                                     const float* __restrict__ ssp2,
                                                     float* __restrict__ out) {
    const int b = blockIdx.x;     // 0..127
    const int i = threadIdx.x;    // 0..255  (hidden unit)

    float hv = 0.0f;
#pragma unroll 4
    for (int s = 0; s < NSPLIT; ++s)
        hv += g_P[((size_t)s * BATCH + b) * HID + i];

    // selu (jax defaults)
    const float SC = 1.0507009873554805f, AL = 1.6732632423543772f;
    float a = (hv > 0.0f) ? SC * hv : SC * (AL * expm1f(hv));

    float sig = 1.0f / (1.0f + expf(-a));
    float sl  = a * sig;

    float bb[11];
    bspline8(a, bb);

    float contrib[OUT2];
#pragma unroll
    for (int o = 0; o < OUT2; ++o) {
        const float* c = coef2 + ((size_t)o * HID + i) * NB;
        float dot = 0.0f;
#pragma unroll
        for (int g = 0; g < NB; ++g) dot += bb[g] * c[g];
        contrib[o] = sb2[o * HID + i] * sl + ssp2[o * HID + i] * dot;
    }

    __shared__ float red[OUT2][HID];
#pragma unroll
    for (int o = 0; o < OUT2; ++o) red[o][i] = contrib[o];
    __syncthreads();
    for (int st = HID / 2; st > 0; st >>= 1) {
        if (i < st) {
#pragma unroll
            for (int o = 0; o < OUT2; ++o) red[o][i] += red[o][i + st];
        }
        __syncthreads();
    }
    if (i < OUT2) out[b * OUT2 + i] = red[i][0];
}

// ---------------- launch ----------------
extern "C" void kernel_launch(void* const* d_in, const int* in_sizes, int n_in,
                              void* d_out, int out_size) {
    const float* x     = (const float*)d_in[0];
    const float* coef1 = (const float*)d_in[1];
    const float* sb1   = (const float*)d_in[2];
    const float* ssp1  = (const float*)d_in[3];
    const float* coef2 = (const float*)d_in[4];
    const float* sb2   = (const float*)d_in[5];
    const float* ssp2  = (const float*)d_in[6];
    float* out = (float*)d_out;

    basis_kernel<<<(BATCH * IN1 + 255) / 256, 256>>>(x);

    cudaFuncSetAttribute(gemm_kernel, cudaFuncAttributeMaxDynamicSharedMemorySize, SMEM_BYTES);
    gemm_kernel<<<dim3(NTILE_N, NSPLIT), 256, SMEM_BYTES>>>(coef1, ssp1, sb1);

    layer2_kernel<<<BATCH, 256>>>(coef2, sb2, ssp2, out);
}